// round 4
// baseline (speedup 1.0000x reference)
#include <cuda_runtime.h>
#include <math.h>

#define NT 256
#define ROWS 16
#define L 336
#define OFF_MU (1024*96*7)
#define OFF_LV (OFF_MU + 7168*64)
#define OFF_LD (OFF_LV + 7168*64)

// smem pool layout (floats)
#define P_XN    0        // xn[16][336]; later r2[16][512] at 0..8192
#define P_INP   5376     // inp[16][192] = [z | h]   5376..8448
#define P_B     8448     // ml[16][128] / r1[16][256] / recon[16][96]
#define P_PB    12544    // pbar[16][16]
#define P_WT    12800    // weight tiles: max(2*16*132, 2*8*260) = 4224
#define P_MEAN  17024
#define P_STD   17040
#define P_SCALE 17056
#define SMEM_FLOATS 17072
#define SMEM_BYTES (SMEM_FLOATS*4)

__device__ float g_Wsc[128*336];
__device__ float g_Wr3[128*512];
__device__ float g_Wml[128*128];
__device__ float g_bml[128];
__device__ float g_Wc[128*16];
__device__ float g_bc[128];
__device__ double g_uhat[8*64];
__device__ double g_cflow[8];
__device__ float g_short[7168*96];   // shortcut scratch (gmem)

__global__ void prep_kernel(const float* __restrict__ W_sc,
                            const float* __restrict__ W_mu, const float* __restrict__ b_mu,
                            const float* __restrict__ W_lv, const float* __restrict__ b_lv,
                            const float* __restrict__ W_r3,
                            const float* __restrict__ W_fu, const float* __restrict__ b_fu,
                            const float* __restrict__ W_ts, const float* __restrict__ b_ts,
                            const float* __restrict__ flow_u, const float* __restrict__ flow_w)
{
    int idx = blockIdx.x * blockDim.x + threadIdx.x;
    int stride = gridDim.x * blockDim.x;
    const int E0 = 128*336;
    const int E1 = E0 + 128*512;
    const int E2 = E1 + 128*128;
    const int E3 = E2 + 128;
    const int E4 = E3 + 128*16;
    const int E5 = E4 + 128;
    const int E6 = E5 + 8;
    for (int i = idx; i < E6; i += stride) {
        if (i < E0) {
            g_Wsc[i] = (i < 96*336) ? W_sc[i] : 0.f;
        } else if (i < E1) {
            int j = i - E0;
            g_Wr3[j] = (j < 96*512) ? W_r3[j] : 0.f;
        } else if (i < E2) {
            int j = i - E1;
            int m = j >> 7, k = j & 127;
            g_Wml[j] = (m < 64) ? W_mu[m*128 + k] : W_lv[(m-64)*128 + k];
        } else if (i < E3) {
            int j = i - E2;
            g_bml[j] = (j < 64) ? b_mu[j] : b_lv[j-64];
        } else if (i < E4) {
            int j = i - E3;
            int h = j >> 4, l = j & 15;
            float s = 0.f;
            for (int d = 0; d < 128; d++) s += W_fu[h*256 + d] * W_ts[d*16 + l];
            g_Wc[j] = s;
        } else if (i < E5) {
            int h = i - E4;
            float s = 0.f;
            for (int d = 0; d < 128; d++) s += W_fu[h*256 + d] * b_ts[d];
            g_bc[h] = s + b_fu[h];
        } else {
            int fi = i - E5;
            double s = 0.0, wsq = 0.0;
            for (int d = 0; d < 64; d++) {
                double u = (double)flow_u[fi*64+d], w = (double)flow_w[fi*64+d];
                s += u*w; wsq += w*w;
            }
            double sp = (s > 0.0) ? s + log1p(exp(-s)) : log1p(exp(s));
            double m = -1.0 + sp;
            double coef = m / (wsq + 1e-6);
            for (int d = 0; d < 64; d++)
                g_uhat[fi*64+d] = (double)flow_u[fi*64+d] + coef*(double)flow_w[fi*64+d];
            g_cflow[fi] = s + coef * wsq;
        }
    }
}

__device__ __forceinline__ float gelu_f(float x) {
    return 0.5f * x * (1.f + erff(x * 0.70710678118654752f));
}

// Block-cooperative GEMM: OUT[16 x M] = IN[16 x K] @ W[M x K]^T + bias, optional GELU.
// B = m-block width (128 or 256), KT = k-tile depth (16 or 8).
// Microtile: R rows x 4 cols, float4 LDS on both operands; double-buffered
// weight tiles with register prefetch (one barrier per k-tile).
// Requires K % KT == 0, M % B == 0 (pad W rows), Mreal % 4 == 0.
template<int B, int KT>
__device__ __forceinline__ void gemm_t(
    const float* smIn, int pitch, int K,
    const float* __restrict__ Wg, const float* __restrict__ bias,
    int M, int Mreal, float* smOut, int opitch, int act, float* Wt)
{
    constexpr int TC = B/4;        // thread columns
    constexpr int RG = 256/TC;     // row groups
    constexpr int R  = 16/RG;      // rows per thread
    constexpr int PITCH = B + 4;   // float4-aligned, swizzle-free pitch
    constexpr int BUFSZ = KT*PITCH;
    constexpr int MST = 256/KT;    // staging m-stride
    const int tid = threadIdx.x;
    const int kk_st = tid & (KT-1);
    const int mmst  = tid / KT;
    const int tcid = tid & (TC-1);
    const int rgid = tid / TC;
    const int c0 = tcid*4;
    const float* inr[R];
    #pragma unroll
    for (int r = 0; r < R; r++) inr[r] = smIn + (rgid*R + r)*pitch;
    const int T = K / KT;
    for (int m0 = 0; m0 < M; m0 += B) {
        const float* Wsrc = Wg + (size_t)(m0 + mmst)*K + kk_st;
        float pf[8];
        #pragma unroll
        for (int s = 0; s < 8; s++) pf[s] = Wsrc[(size_t)(MST*s)*K];
        __syncthreads();                    // prior users of Wt done
        #pragma unroll
        for (int s = 0; s < 8; s++) Wt[kk_st*PITCH + mmst + MST*s] = pf[s];
        if (T > 1) {
            #pragma unroll
            for (int s = 0; s < 8; s++) pf[s] = Wsrc[(size_t)(MST*s)*K + KT];
        }
        __syncthreads();                    // tile 0 ready
        float4 acc[R];
        #pragma unroll
        for (int r = 0; r < R; r++) acc[r] = make_float4(0.f,0.f,0.f,0.f);
        int buf = 0;
        for (int t = 0; t < T; t++) {
            const float* W = Wt + buf*BUFSZ;
            #pragma unroll
            for (int g = 0; g < KT/4; g++) {
                float xq[R][4];
                #pragma unroll
                for (int r = 0; r < R; r++) {
                    float4 xv = *(const float4*)(inr[r] + t*KT + g*4);
                    xq[r][0]=xv.x; xq[r][1]=xv.y; xq[r][2]=xv.z; xq[r][3]=xv.w;
                }
                #pragma unroll
                for (int j = 0; j < 4; j++) {
                    float4 w = *(const float4*)&W[(g*4+j)*PITCH + c0];
                    #pragma unroll
                    for (int r = 0; r < R; r++) {
                        acc[r].x = fmaf(xq[r][j], w.x, acc[r].x);
                        acc[r].y = fmaf(xq[r][j], w.y, acc[r].y);
                        acc[r].z = fmaf(xq[r][j], w.z, acc[r].z);
                        acc[r].w = fmaf(xq[r][j], w.w, acc[r].w);
                    }
                }
            }
            if (t + 1 < T) {
                float* Wd = Wt + (buf^1)*BUFSZ;
                #pragma unroll
                for (int s = 0; s < 8; s++) Wd[kk_st*PITCH + mmst + MST*s] = pf[s];
                if (t + 2 < T) {
                    #pragma unroll
                    for (int s = 0; s < 8; s++) pf[s] = Wsrc[(size_t)(MST*s)*K + (size_t)(t+2)*KT];
                }
            }
            __syncthreads();
            buf ^= 1;
        }
        int m = m0 + c0;
        if (m < Mreal) {
            float4 bb = *(const float4*)&bias[m];
            #pragma unroll
            for (int r = 0; r < R; r++) {
                float4 v;
                v.x = acc[r].x + bb.x; v.y = acc[r].y + bb.y;
                v.z = acc[r].z + bb.z; v.w = acc[r].w + bb.w;
                if (act) { v.x=gelu_f(v.x); v.y=gelu_f(v.y); v.z=gelu_f(v.z); v.w=gelu_f(v.w); }
                *(float4*)&smOut[(size_t)(rgid*R + r)*opitch + m] = v;
            }
        }
    }
}

__global__ void __launch_bounds__(NT, 3) fused_kernel(
    const float* __restrict__ x_enc, const float* __restrict__ eps,
    const float* __restrict__ p_aw, const float* __restrict__ p_ab,
    const float* __restrict__ b_sc,
    const float* __restrict__ W_r1, const float* __restrict__ b_r1,
    const float* __restrict__ W_r2, const float* __restrict__ b_r2,
    const float* __restrict__ b_r3,
    const float* __restrict__ flow_w, const float* __restrict__ flow_b,
    float* __restrict__ out)
{
    extern __shared__ float smn[];
    float* sA    = smn + P_XN;
    float* sINP  = smn + P_INP;
    float* sB    = smn + P_B;
    float* sPB   = smn + P_PB;
    float* sWT   = smn + P_WT;
    float* sMean = smn + P_MEAN;
    float* sStd  = smn + P_STD;
    float* sScale= smn + P_SCALE;

    int tid = threadIdx.x;
    int n0 = blockIdx.x * ROWS;
    float aw = p_aw[0], ab = p_ab[0];
    int warp = tid >> 5, lane = tid & 31;

    // ---- 1. load x (x_enc[b][l][c] -> xn_raw[r][l], n = b*7+c) ----
    for (int t = tid; t < ROWS*L; t += NT) {
        int r = t & 15, l = t >> 4;
        int n = n0 + r;
        int b = n / 7, c = n - b*7;
        sA[r*L + l] = x_enc[(b*L + l)*7 + c];
    }
    __syncthreads();

    // ---- 2. per-row mean/std (warp w handles rows 2w, 2w+1) ----
    #pragma unroll
    for (int rr = 0; rr < 2; rr++) {
        int r = warp*2 + rr;
        const float* row = sA + r*L;
        float s = 0.f, sq = 0.f;
        for (int l2 = lane; l2 < L; l2 += 32) { float v = row[l2]; s += v; sq += v*v; }
        #pragma unroll
        for (int o = 16; o > 0; o >>= 1) {
            s  += __shfl_xor_sync(0xffffffffu, s, o);
            sq += __shfl_xor_sync(0xffffffffu, sq, o);
        }
        if (lane == 0) {
            float mean = s * (1.f/336.f);
            float var = sq * (1.f/336.f) - mean*mean;
            float sd = sqrtf(var + 1e-5f);
            sMean[r] = mean; sStd[r] = sd; sScale[r] = aw / sd;
        }
    }
    __syncthreads();

    // ---- 3. normalize in place ----
    for (int t = tid; t < ROWS*L; t += NT) {
        int r = t / L;
        sA[t] = (sA[t] - sMean[r]) * sScale[r] + ab;
    }
    __syncthreads();

    // ---- 4. pbar[r][j] = mean over 41 patches of xn[r][8p+j] ----
    {
        int r = tid >> 4, j = tid & 15;
        float s = 0.f;
        #pragma unroll
        for (int pp = 0; pp < 41; pp++) s += sA[r*L + pp*8 + j];
        sPB[r*16 + j] = s * (1.f/41.f);
    }
    // (gemm_t's internal barriers order pbar/xn writes before any read)

    // ---- 5. shortcut = xn @ Wsc^T + b_sc  -> gmem scratch ----
    gemm_t<128,16>(sA, L, L, g_Wsc, b_sc, 128, 96, g_short + (size_t)n0*96, 96, 0, sWT);
    // ---- 6. h = pbar @ Wc^T + bc  -> inp[:,64:192] ----
    gemm_t<128,16>(sPB, 16, 16, g_Wc, g_bc, 128, 128, sINP + 64, 192, 0, sWT);
    // ---- 7. [mu|lv] = h @ Wml^T + bml ----
    gemm_t<128,16>(sINP + 64, 192, 128, g_Wml, g_bml, 128, 128, sB, 128, 0, sWT);
    __syncthreads();

    // ---- 8+9. reparam (FP64) + planar flows (FP64 scalar chain).
    // Warp per row: rows warp and warp+8. Lane handles dims lane and 32+lane.
    #pragma unroll
    for (int rr = 0; rr < 2; rr++) {
        int r = warp + rr*8;
        int n = n0 + r;
        float mu0 = sB[r*128 + lane];
        float mu1 = sB[r*128 + 32 + lane];
        float lv0 = sB[r*128 + 64 + lane];
        float lv1 = sB[r*128 + 96 + lane];
        out[OFF_MU + n*64 + lane]      = mu0;
        out[OFF_MU + n*64 + 32 + lane] = mu1;
        out[OFF_LV + n*64 + lane]      = lv0;
        out[OFF_LV + n*64 + 32 + lane] = lv1;
        double z0 = (double)mu0 + (double)eps[n*64 + lane]      * exp(0.5 * (double)lv0);
        double z1 = (double)mu1 + (double)eps[n*64 + 32 + lane] * exp(0.5 * (double)lv1);
        double ld = 0.0;
        #pragma unroll
        for (int i = 0; i < 8; i++) {
            double w0 = (double)flow_w[i*64 + lane];
            double w1 = (double)flow_w[i*64 + 32 + lane];
            double dot = z0*w0 + z1*w1;
            #pragma unroll
            for (int o = 16; o > 0; o >>= 1) dot += __shfl_xor_sync(0xffffffffu, dot, o);
            double th = tanh(dot + (double)flow_b[i]);
            z0 += th * g_uhat[i*64 + lane];
            z1 += th * g_uhat[i*64 + 32 + lane];
            ld += log(fabs(1.0 + (1.0 - th*th) * g_cflow[i]) + 1e-6);
        }
        sINP[r*192 + lane]      = (float)z0;
        sINP[r*192 + 32 + lane] = (float)z1;
        if (lane == 0) out[OFF_LD + n] = (float)ld;
    }
    // (flows write sINP; gemm internal barriers order before compute)

    // ---- 10-12. decoder ----
    gemm_t<256,8>(sINP, 192, 192, W_r1, b_r1, 256, 256, sB, 256, 1, sWT);   // r1 (gelu)
    gemm_t<256,8>(sB, 256, 256, W_r2, b_r2, 512, 512, sA, 512, 1, sWT);     // r2 (gelu)
    gemm_t<128,16>(sA, 512, 512, g_Wr3, b_r3, 128, 96, sB, 96, 0, sWT);     // recon
    __syncthreads();

    // ---- 13. denorm + scatter out[b][p][c] ----
    float inv_aw = 1.f / (aw + 1e-10f);
    for (int t = tid; t < ROWS*96; t += NT) {
        int r = t & 15, pcol = t >> 4;
        int n = n0 + r;
        float v = sB[r*96 + pcol] + g_short[(size_t)n*96 + pcol];
        float den = fmaf((v - ab) * inv_aw, sStd[r], sMean[r]);
        int b = n/7, c = n - b*7;
        out[(b*96 + pcol)*7 + c] = den;
    }
}

extern "C" void kernel_launch(void* const* d_in, const int* in_sizes, int n_in,
                              void* d_out, int out_size) {
    const float* x_enc  = (const float*)d_in[0];
    const float* eps    = (const float*)d_in[1];
    const float* aw     = (const float*)d_in[2];
    const float* ab     = (const float*)d_in[3];
    const float* W_sc   = (const float*)d_in[4];
    const float* b_sc   = (const float*)d_in[5];
    const float* W_ts   = (const float*)d_in[6];
    const float* b_ts   = (const float*)d_in[7];
    const float* W_fu   = (const float*)d_in[8];
    const float* b_fu   = (const float*)d_in[9];
    const float* W_mu   = (const float*)d_in[10];
    const float* b_mu   = (const float*)d_in[11];
    const float* W_lv   = (const float*)d_in[12];
    const float* b_lv   = (const float*)d_in[13];
    const float* flow_u = (const float*)d_in[14];
    const float* flow_w = (const float*)d_in[15];
    const float* flow_b = (const float*)d_in[16];
    const float* W_r1   = (const float*)d_in[17];
    const float* b_r1   = (const float*)d_in[18];
    const float* W_r2   = (const float*)d_in[19];
    const float* b_r2   = (const float*)d_in[20];
    const float* W_r3   = (const float*)d_in[21];
    const float* b_r3   = (const float*)d_in[22];
    float* out = (float*)d_out;

    cudaFuncSetAttribute(fused_kernel, cudaFuncAttributeMaxDynamicSharedMemorySize, SMEM_BYTES);

    prep_kernel<<<128, 256>>>(W_sc, W_mu, b_mu, W_lv, b_lv, W_r3,
                              W_fu, b_fu, W_ts, b_ts, flow_u, flow_w);
    fused_kernel<<<448, NT, SMEM_BYTES>>>(x_enc, eps, aw, ab, b_sc,
                                          W_r1, b_r1, W_r2, b_r2, b_r3,
                                          flow_w, flow_b, out);
}

// round 6
// speedup vs baseline: 1.1223x; 1.1223x over previous
#include <cuda_runtime.h>
#include <math.h>

#define NT 256
#define ROWS 16
#define L 336
#define OFF_MU (1024*96*7)
#define OFF_LV (OFF_MU + 7168*64)
#define OFF_LD (OFF_LV + 7168*64)

// smem pool layout (floats)
// sA [0..5680): xn[16][336] (pitch 336); sINP[16][192] aliases [0..3072);
//              r2-chunk[16][256] aliases [0..4096); recon[16][96] aliases [0..1536);
//              pbar[16][16] at 5376; stats (mean/std/scale) at 5632.
#define P_A     0
#define P_PB    5376
#define P_MEAN  5632
#define P_STD   5648
#define P_SCALE 5664
#define P_B     5696     // ml[16][128] / r1[16][256]  (4096)
#define P_WT    9792     // weight tiles 2 x [16][130] = 4160
#define SMEM_FLOATS 13952
#define SMEM_BYTES (SMEM_FLOATS*4)

__device__ float g_Wsc[128*336];
__device__ float g_Wr3[128*512];
__device__ float g_Wml[128*128];
__device__ float g_bml[128];
__device__ float g_Wc[128*16];
__device__ float g_bc[128];
__device__ double g_uhat[8*64];
__device__ double g_cflow[8];
__device__ float g_short[7168*96];   // shortcut scratch (gmem)

__global__ void prep_kernel(const float* __restrict__ W_sc,
                            const float* __restrict__ W_mu, const float* __restrict__ b_mu,
                            const float* __restrict__ W_lv, const float* __restrict__ b_lv,
                            const float* __restrict__ W_r3,
                            const float* __restrict__ W_fu, const float* __restrict__ b_fu,
                            const float* __restrict__ W_ts, const float* __restrict__ b_ts,
                            const float* __restrict__ flow_u, const float* __restrict__ flow_w)
{
    int idx = blockIdx.x * blockDim.x + threadIdx.x;
    int stride = gridDim.x * blockDim.x;
    const int E0 = 128*336;
    const int E1 = E0 + 128*512;
    const int E2 = E1 + 128*128;
    const int E3 = E2 + 128;
    const int E4 = E3 + 128*16;
    const int E5 = E4 + 128;
    const int E6 = E5 + 8;
    for (int i = idx; i < E6; i += stride) {
        if (i < E0) {
            g_Wsc[i] = (i < 96*336) ? W_sc[i] : 0.f;
        } else if (i < E1) {
            int j = i - E0;
            g_Wr3[j] = (j < 96*512) ? W_r3[j] : 0.f;
        } else if (i < E2) {
            int j = i - E1;
            int m = j >> 7, k = j & 127;
            g_Wml[j] = (m < 64) ? W_mu[m*128 + k] : W_lv[(m-64)*128 + k];
        } else if (i < E3) {
            int j = i - E2;
            g_bml[j] = (j < 64) ? b_mu[j] : b_lv[j-64];
        } else if (i < E4) {
            int j = i - E3;
            int h = j >> 4, l = j & 15;
            float s = 0.f;
            for (int d = 0; d < 128; d++) s += W_fu[h*256 + d] * W_ts[d*16 + l];
            g_Wc[j] = s;
        } else if (i < E5) {
            int h = i - E4;
            float s = 0.f;
            for (int d = 0; d < 128; d++) s += W_fu[h*256 + d] * b_ts[d];
            g_bc[h] = s + b_fu[h];
        } else {
            int fi = i - E5;
            double s = 0.0, wsq = 0.0;
            for (int d = 0; d < 64; d++) {
                double u = (double)flow_u[fi*64+d], w = (double)flow_w[fi*64+d];
                s += u*w; wsq += w*w;
            }
            double sp = (s > 0.0) ? s + log1p(exp(-s)) : log1p(exp(s));
            double m = -1.0 + sp;
            double coef = m / (wsq + 1e-6);
            for (int d = 0; d < 64; d++)
                g_uhat[fi*64+d] = (double)flow_u[fi*64+d] + coef*(double)flow_w[fi*64+d];
            g_cflow[fi] = s + coef * wsq;
        }
    }
}

__device__ __forceinline__ float gelu_f(float x) {
    return 0.5f * x * (1.f + erff(x * 0.70710678118654752f));
}

// Block-cooperative GEMM: acc[16 x M] (+)= IN[16 x K] @ W[:, kwoff:kwoff+K]^T.
// R3-proven core: float2 4x2 microtile, KT=16, double-buffered weight tiles,
// register prefetch, one barrier per k-tile.
// wstride = W row stride; kwoff = column offset into W's K dim.
// acc[8] is caller-persistent (layout [row 0..3][col 0..1]); init zeroes it,
// fin adds bias (+GELU) and stores to smOut. M multiple-of-128 loop bound
// (W padded to >= that many rows); Mreal = valid output cols.
__device__ __forceinline__ void gemm_f2(
    const float* smIn, int pitch, int K, int wstride, int kwoff,
    const float* __restrict__ Wg, const float* __restrict__ bias,
    int M, int Mreal, float* smOut, int opitch, int act, float* Wt,
    float* acc, int init, int fin)
{
    int tid = threadIdx.x;
    int rg = tid >> 6;             // 0..3 -> rows rg*4 .. rg*4+3
    int mloc = (tid & 63) << 1;    // 0..126 even
    int kk_st = tid & 15;          // staging: column kk_st
    int mm0 = tid >> 4;            // staging: rows mm0 + 16*s
    const float* in0 = smIn + (rg*4 + 0)*pitch;
    const float* in1 = in0 + pitch;
    const float* in2 = in1 + pitch;
    const float* in3 = in2 + pitch;
    int T = K >> 4;
    for (int m0 = 0; m0 < M; m0 += 128) {
        const float* Wsrc = Wg + (size_t)m0*wstride + kwoff + kk_st;
        float pf[8];
        #pragma unroll
        for (int s = 0; s < 8; s++) pf[s] = Wsrc[(size_t)(mm0 + 16*s)*wstride];
        __syncthreads();                       // prior users of Wt done
        #pragma unroll
        for (int s = 0; s < 8; s++) Wt[kk_st*130 + mm0 + 16*s] = pf[s];
        if (T > 1) {
            #pragma unroll
            for (int s = 0; s < 8; s++) pf[s] = Wsrc[(size_t)(mm0 + 16*s)*wstride + 16];
        }
        __syncthreads();                       // tile 0 ready
        if (init) {
            #pragma unroll
            for (int i = 0; i < 8; i++) acc[i] = 0.f;
        }
        int buf = 0;
        for (int t = 0; t < T; t++) {
            const float* W = Wt + buf*2080;
            const float* i0 = in0 + t*16;
            const float* i1 = in1 + t*16;
            const float* i2 = in2 + t*16;
            const float* i3 = in3 + t*16;
            #pragma unroll
            for (int kk = 0; kk < 16; kk += 2) {
                float2 w0 = *(const float2*)&W[kk*130 + mloc];
                float2 w1 = *(const float2*)&W[(kk+1)*130 + mloc];
                float2 x0 = *(const float2*)(i0 + kk);
                float2 x1 = *(const float2*)(i1 + kk);
                float2 x2 = *(const float2*)(i2 + kk);
                float2 x3 = *(const float2*)(i3 + kk);
                acc[0] = fmaf(x0.x, w0.x, acc[0]); acc[0] = fmaf(x0.y, w1.x, acc[0]);
                acc[1] = fmaf(x0.x, w0.y, acc[1]); acc[1] = fmaf(x0.y, w1.y, acc[1]);
                acc[2] = fmaf(x1.x, w0.x, acc[2]); acc[2] = fmaf(x1.y, w1.x, acc[2]);
                acc[3] = fmaf(x1.x, w0.y, acc[3]); acc[3] = fmaf(x1.y, w1.y, acc[3]);
                acc[4] = fmaf(x2.x, w0.x, acc[4]); acc[4] = fmaf(x2.y, w1.x, acc[4]);
                acc[5] = fmaf(x2.x, w0.y, acc[5]); acc[5] = fmaf(x2.y, w1.y, acc[5]);
                acc[6] = fmaf(x3.x, w0.x, acc[6]); acc[6] = fmaf(x3.y, w1.x, acc[6]);
                acc[7] = fmaf(x3.x, w0.y, acc[7]); acc[7] = fmaf(x3.y, w1.y, acc[7]);
            }
            if (t + 1 < T) {
                float* Wd = Wt + (buf^1)*2080;
                #pragma unroll
                for (int s = 0; s < 8; s++) Wd[kk_st*130 + mm0 + 16*s] = pf[s];
                if (t + 2 < T) {
                    #pragma unroll
                    for (int s = 0; s < 8; s++) pf[s] = Wsrc[(size_t)(mm0 + 16*s)*wstride + (t+2)*16];
                }
            }
            __syncthreads();
            buf ^= 1;
        }
        int m = m0 + mloc;
        if (fin && m < Mreal) {
            float b0 = bias[m], b1 = bias[m+1];
            int r0 = rg*4;
            float v;
            v = acc[0] + b0; if (act) v = gelu_f(v); smOut[(r0+0)*opitch + m]   = v;
            v = acc[1] + b1; if (act) v = gelu_f(v); smOut[(r0+0)*opitch + m+1] = v;
            v = acc[2] + b0; if (act) v = gelu_f(v); smOut[(r0+1)*opitch + m]   = v;
            v = acc[3] + b1; if (act) v = gelu_f(v); smOut[(r0+1)*opitch + m+1] = v;
            v = acc[4] + b0; if (act) v = gelu_f(v); smOut[(r0+2)*opitch + m]   = v;
            v = acc[5] + b1; if (act) v = gelu_f(v); smOut[(r0+2)*opitch + m+1] = v;
            v = acc[6] + b0; if (act) v = gelu_f(v); smOut[(r0+3)*opitch + m]   = v;
            v = acc[7] + b1; if (act) v = gelu_f(v); smOut[(r0+3)*opitch + m+1] = v;
        }
    }
}

__global__ void __launch_bounds__(NT, 4) fused_kernel(
    const float* __restrict__ x_enc, const float* __restrict__ eps,
    const float* __restrict__ p_aw, const float* __restrict__ p_ab,
    const float* __restrict__ b_sc,
    const float* __restrict__ W_r1, const float* __restrict__ b_r1,
    const float* __restrict__ W_r2, const float* __restrict__ b_r2,
    const float* __restrict__ b_r3,
    const float* __restrict__ flow_w, const float* __restrict__ flow_b,
    float* __restrict__ out)
{
    extern __shared__ float smn[];
    float* sA    = smn + P_A;       // xn / sINP alias / r2-chunk / recon
    float* sINP  = smn + P_A;       // [z | h], pitch 192, aliases xn
    float* sPB   = smn + P_PB;
    float* sMean = smn + P_MEAN;
    float* sStd  = smn + P_STD;
    float* sScale= smn + P_SCALE;
    float* sB    = smn + P_B;
    float* sWT   = smn + P_WT;

    int tid = threadIdx.x;
    int n0 = blockIdx.x * ROWS;
    float aw = p_aw[0], ab = p_ab[0];
    int warp = tid >> 5, lane = tid & 31;
    float acc[8];

    // ---- 1. load x (x_enc[b][l][c] -> xn_raw[r][l], n = b*7+c) ----
    for (int t = tid; t < ROWS*L; t += NT) {
        int r = t & 15, l = t >> 4;
        int n = n0 + r;
        int b = n / 7, c = n - b*7;
        sA[r*L + l] = x_enc[(b*L + l)*7 + c];
    }
    __syncthreads();

    // ---- 2. per-row mean/std (warp w handles rows 2w, 2w+1) ----
    #pragma unroll
    for (int rr = 0; rr < 2; rr++) {
        int r = warp*2 + rr;
        const float* row = sA + r*L;
        float s = 0.f, sq = 0.f;
        for (int l2 = lane; l2 < L; l2 += 32) { float v = row[l2]; s += v; sq += v*v; }
        #pragma unroll
        for (int o = 16; o > 0; o >>= 1) {
            s  += __shfl_xor_sync(0xffffffffu, s, o);
            sq += __shfl_xor_sync(0xffffffffu, sq, o);
        }
        if (lane == 0) {
            float mean = s * (1.f/336.f);
            float var = sq * (1.f/336.f) - mean*mean;
            float sd = sqrtf(var + 1e-5f);
            sMean[r] = mean; sStd[r] = sd; sScale[r] = aw / sd;
        }
    }
    __syncthreads();

    // ---- 3. normalize in place ----
    for (int t = tid; t < ROWS*L; t += NT) {
        int r = t / L;
        sA[t] = (sA[t] - sMean[r]) * sScale[r] + ab;
    }
    __syncthreads();

    // ---- 4. pbar[r][j] = mean over 41 patches of xn[r][8p+j] ----
    {
        int r = tid >> 4, j = tid & 15;
        float s = 0.f;
        #pragma unroll
        for (int pp = 0; pp < 41; pp++) s += sA[r*L + pp*8 + j];
        sPB[r*16 + j] = s * (1.f/41.f);
    }
    // (gemm_f2's internal barriers order pbar/xn writes before any read)

    // ---- 5. shortcut = xn @ Wsc^T + b_sc  -> gmem scratch ----
    gemm_f2(sA, L, L, L, 0, g_Wsc, b_sc, 96, 96,
            g_short + (size_t)n0*96, 96, 0, sWT, acc, 1, 1);
    // ---- 6. h = pbar @ Wc^T + bc  -> inp[:,64:192] (aliases dead xn) ----
    gemm_f2(sPB, 16, 16, 16, 0, g_Wc, g_bc, 128, 128, sINP + 64, 192, 0, sWT, acc, 1, 1);
    // ---- 7. [mu|lv] = h @ Wml^T + bml ----
    gemm_f2(sINP + 64, 192, 128, 128, 0, g_Wml, g_bml, 128, 128, sB, 128, 0, sWT, acc, 1, 1);
    __syncthreads();

    // ---- 8+9. reparam (FP64) + planar flows (FP64 scalar chain).
    // Warp per row: rows warp and warp+8. Lane handles dims lane and 32+lane.
    #pragma unroll
    for (int rr = 0; rr < 2; rr++) {
        int r = warp + rr*8;
        int n = n0 + r;
        float mu0 = sB[r*128 + lane];
        float mu1 = sB[r*128 + 32 + lane];
        float lv0 = sB[r*128 + 64 + lane];
        float lv1 = sB[r*128 + 96 + lane];
        out[OFF_MU + n*64 + lane]      = mu0;
        out[OFF_MU + n*64 + 32 + lane] = mu1;
        out[OFF_LV + n*64 + lane]      = lv0;
        out[OFF_LV + n*64 + 32 + lane] = lv1;
        double z0 = (double)mu0 + (double)eps[n*64 + lane]      * exp(0.5 * (double)lv0);
        double z1 = (double)mu1 + (double)eps[n*64 + 32 + lane] * exp(0.5 * (double)lv1);
        double ld = 0.0;
        #pragma unroll
        for (int i = 0; i < 8; i++) {
            double w0 = (double)flow_w[i*64 + lane];
            double w1 = (double)flow_w[i*64 + 32 + lane];
            double dot = z0*w0 + z1*w1;
            #pragma unroll
            for (int o = 16; o > 0; o >>= 1) dot += __shfl_xor_sync(0xffffffffu, dot, o);
            double th = tanh(dot + (double)flow_b[i]);
            z0 += th * g_uhat[i*64 + lane];
            z1 += th * g_uhat[i*64 + 32 + lane];
            ld += log(fabs(1.0 + (1.0 - th*th) * g_cflow[i]) + 1e-6);
        }
        sINP[r*192 + lane]      = (float)z0;
        sINP[r*192 + 32 + lane] = (float)z1;
        if (lane == 0) out[OFF_LD + n] = (float)ld;
    }
    // (flows write sINP; gemm internal barriers order before compute)

    // ---- 10. r1 = gelu(inp @ Wr1^T + br1) -> sB ----
    gemm_f2(sINP, 192, 192, 192, 0, W_r1, b_r1, 256, 256, sB, 256, 1, sWT, acc, 1, 1);

    // ---- 11+12. r2 (chunked 2x256) fused with r3 accumulation ----
    {
        float acc3[8];
        #pragma unroll
        for (int c = 0; c < 2; c++) {
            // r2 chunk: rows 256c..256c+256 of W_r2 -> gelu -> sA[16][256]
            gemm_f2(sB, 256, 256, 256, 0, W_r2 + (size_t)(256*c)*256, b_r2 + 256*c,
                    256, 256, sA, 256, 1, sWT, acc, 1, 1);
            // r3 partial: acc3 += r2chunk @ Wr3[:, 256c:256c+256]^T
            gemm_f2(sA, 256, 256, 512, 256*c, g_Wr3, b_r3, 96, 96,
                    sA, 96, 0, sWT, acc3, c == 0, c == 1);
        }
    }
    __syncthreads();

    // ---- 13. denorm + scatter out[b][p][c] (recon now in sA[16][96]) ----
    float inv_aw = 1.f / (aw + 1e-10f);
    for (int t = tid; t < ROWS*96; t += NT) {
        int r = t & 15, pcol = t >> 4;
        int n = n0 + r;
        float v = sA[r*96 + pcol] + g_short[(size_t)n*96 + pcol];
        float den = fmaf((v - ab) * inv_aw, sStd[r], sMean[r]);
        int b = n/7, c = n - b*7;
        out[(b*96 + pcol)*7 + c] = den;
    }
}

extern "C" void kernel_launch(void* const* d_in, const int* in_sizes, int n_in,
                              void* d_out, int out_size) {
    const float* x_enc  = (const float*)d_in[0];
    const float* eps    = (const float*)d_in[1];
    const float* aw     = (const float*)d_in[2];
    const float* ab     = (const float*)d_in[3];
    const float* W_sc   = (const float*)d_in[4];
    const float* b_sc   = (const float*)d_in[5];
    const float* W_ts   = (const float*)d_in[6];
    const float* b_ts   = (const float*)d_in[7];
    const float* W_fu   = (const float*)d_in[8];
    const float* b_fu   = (const float*)d_in[9];
    const float* W_mu   = (const float*)d_in[10];
    const float* b_mu   = (const float*)d_in[11];
    const float* W_lv   = (const float*)d_in[12];
    const float* b_lv   = (const float*)d_in[13];
    const float* flow_u = (const float*)d_in[14];
    const float* flow_w = (const float*)d_in[15];
    const float* flow_b = (const float*)d_in[16];
    const float* W_r1   = (const float*)d_in[17];
    const float* b_r1   = (const float*)d_in[18];
    const float* W_r2   = (const float*)d_in[19];
    const float* b_r2   = (const float*)d_in[20];
    const float* W_r3   = (const float*)d_in[21];
    const float* b_r3   = (const float*)d_in[22];
    float* out = (float*)d_out;

    cudaFuncSetAttribute(fused_kernel, cudaFuncAttributeMaxDynamicSharedMemorySize, SMEM_BYTES);

    prep_kernel<<<128, 256>>>(W_sc, W_mu, b_mu, W_lv, b_lv, W_r3,
                              W_fu, b_fu, W_ts, b_ts, flow_u, flow_w);
    fused_kernel<<<448, NT, SMEM_BYTES>>>(x_enc, eps, aw, ab, b_sc,
                                          W_r1, b_r1, W_r2, b_r2, b_r3,
                                          flow_w, flow_b, out);
}

// round 7
// speedup vs baseline: 1.2582x; 1.1211x over previous
#include <cuda_runtime.h>
#include <math.h>
#include <stdint.h>

#define NT 256
#define ROWS 16
#define L 336
#define OFF_MU (1024*96*7)
#define OFF_LV (OFF_MU + 7168*64)
#define OFF_LD (OFF_LV + 7168*64)

// smem pool layout (floats)
#define P_A     0        // xn[16][336]; aliases: sINP[16][192], r2chunk[16][256], recon[16][96]
#define P_PB    5376     // pbar[16][16]
#define P_MEAN  5632
#define P_STD   5648
#define P_SCALE 5664
#define P_B     5680     // ml[16][128] / r1[16][256]  (4096)
#define P_WT    9776     // weight tiles: large 2 x [16][260] = 8320 (small uses 2 x [16][132] subset)
#define SMEM_FLOATS 18096
#define SMEM_BYTES (SMEM_FLOATS*4)

// k-major (transposed) weights
__device__ float g_Wsct[336*128];   // [k][m], m padded 96->128
__device__ float g_Wr3t[512*128];   // [k][m], m padded 96->128
__device__ float g_Wmlt[128*128];   // [k][m], m = [mu(64)|lv(64)]
__device__ float g_bml[128];
__device__ float g_Wct[16*128];     // [l][h]
__device__ float g_bc[128];
__device__ float g_Wr1t[192*256];   // [k][m]
__device__ float g_Wr2t[256*512];   // [k][m]
__device__ double g_uhat[8*64];
__device__ double g_cflow[8];
__device__ float g_short[7168*96];  // shortcut scratch (gmem)

__global__ void prep_kernel(const float* __restrict__ W_sc,
                            const float* __restrict__ W_mu, const float* __restrict__ b_mu,
                            const float* __restrict__ W_lv, const float* __restrict__ b_lv,
                            const float* __restrict__ W_r3,
                            const float* __restrict__ W_fu, const float* __restrict__ b_fu,
                            const float* __restrict__ W_ts, const float* __restrict__ b_ts,
                            const float* __restrict__ flow_u, const float* __restrict__ flow_w,
                            const float* __restrict__ W_r1, const float* __restrict__ W_r2)
{
    int idx = blockIdx.x * blockDim.x + threadIdx.x;
    int stride = gridDim.x * blockDim.x;
    const int S0 = 336*128;          // Wsct
    const int S1 = S0 + 512*128;     // Wr3t
    const int S2 = S1 + 128*128;     // Wmlt
    const int S3 = S2 + 128;         // bml
    const int S4 = S3 + 16*128;      // Wct
    const int S5 = S4 + 128;         // bc
    const int S6 = S5 + 192*256;     // Wr1t
    const int S7 = S6 + 256*512;     // Wr2t
    const int S8 = S7 + 8;           // flows
    for (int i = idx; i < S8; i += stride) {
        if (i < S0) {
            int k = i >> 7, m = i & 127;
            g_Wsct[i] = (m < 96) ? W_sc[m*336 + k] : 0.f;
        } else if (i < S1) {
            int j = i - S0;
            int k = j >> 7, m = j & 127;
            g_Wr3t[j] = (m < 96) ? W_r3[m*512 + k] : 0.f;
        } else if (i < S2) {
            int j = i - S1;
            int k = j >> 7, m = j & 127;
            g_Wmlt[j] = (m < 64) ? W_mu[m*128 + k] : W_lv[(m-64)*128 + k];
        } else if (i < S3) {
            int j = i - S2;
            g_bml[j] = (j < 64) ? b_mu[j] : b_lv[j-64];
        } else if (i < S4) {
            int j = i - S3;
            int l = j >> 7, h = j & 127;
            float s = 0.f;
            for (int d = 0; d < 128; d++) s += W_fu[h*256 + d] * W_ts[d*16 + l];
            g_Wct[j] = s;
        } else if (i < S5) {
            int h = i - S4;
            float s = 0.f;
            for (int d = 0; d < 128; d++) s += W_fu[h*256 + d] * b_ts[d];
            g_bc[h] = s + b_fu[h];
        } else if (i < S6) {
            int j = i - S5;
            int k = j >> 8, m = j & 255;
            g_Wr1t[j] = W_r1[m*192 + k];
        } else if (i < S7) {
            int j = i - S6;
            int k = j >> 9, m = j & 511;
            g_Wr2t[j] = W_r2[m*256 + k];
        } else {
            int fi = i - S7;
            double s = 0.0, wsq = 0.0;
            for (int d = 0; d < 64; d++) {
                double u = (double)flow_u[fi*64+d], w = (double)flow_w[fi*64+d];
                s += u*w; wsq += w*w;
            }
            double sp = (s > 0.0) ? s + log1p(exp(-s)) : log1p(exp(s));
            double m = -1.0 + sp;
            double coef = m / (wsq + 1e-6);
            for (int d = 0; d < 64; d++)
                g_uhat[fi*64+d] = (double)flow_u[fi*64+d] + coef*(double)flow_w[fi*64+d];
            g_cflow[fi] = s + coef * wsq;
        }
    }
}

__device__ __forceinline__ float gelu_f(float x) {
    return 0.5f * x * (1.f + erff(x * 0.70710678118654752f));
}
__device__ __forceinline__ uint32_t smem_u32(const void* p) {
    return (uint32_t)__cvta_generic_to_shared(p);
}
#define CP_ASYNC16(d, s) asm volatile("cp.async.ca.shared.global [%0], [%1], 16;\n" :: "r"(d), "l"(s))
#define CP_COMMIT()      asm volatile("cp.async.commit_group;\n" ::: "memory")
#define CP_WAIT0()       asm volatile("cp.async.wait_group 0;\n" ::: "memory")

// Small GEMM: OUT[16 x <=128] (+)= IN[16 x K] @ Wk (k-major, row stride 128).
// 4x2 microtile, KT=16, cp.async double-buffer, ONE barrier per tile.
// acc[8] caller-persistent; init zeroes, fin adds bias(+GELU) and stores.
__device__ __forceinline__ void gemm_s(
    const float* smIn, int pitch, int K,
    const float* __restrict__ Wk, const float* __restrict__ bias,
    int Mreal, float* smOut, int opitch, int act, float* Wt,
    float* acc, int init, int fin)
{
    const int tid = threadIdx.x;
    const int rg = tid >> 6;
    const int mloc = (tid & 63) << 1;
    const int srow = tid >> 5;            // staging rows srow, srow+8
    const int scol = (tid & 31) << 2;
    const float* in0 = smIn + rg*4*pitch;
    const int T = K >> 4;
    {
        #pragma unroll
        for (int s2 = 0; s2 < 2; s2++) {
            uint32_t d = smem_u32(Wt + (srow + 8*s2)*132 + scol);
            CP_ASYNC16(d, Wk + (size_t)(srow + 8*s2)*128 + scol);
        }
        CP_COMMIT();
    }
    if (init) {
        #pragma unroll
        for (int i = 0; i < 8; i++) acc[i] = 0.f;
    }
    int buf = 0;
    for (int t = 0; t < T; t++) {
        CP_WAIT0();
        __syncthreads();            // tile t visible; tile t-1 consumers all done
        if (t + 1 < T) {
            const float* g = Wk + (size_t)((t+1)*16)*128;
            float* Wd = Wt + (buf^1)*2112;
            #pragma unroll
            for (int s2 = 0; s2 < 2; s2++) {
                uint32_t d = smem_u32(Wd + (srow + 8*s2)*132 + scol);
                CP_ASYNC16(d, g + (size_t)(srow + 8*s2)*128 + scol);
            }
            CP_COMMIT();
        }
        const float* W = Wt + buf*2112;
        const float* i0 = in0 + t*16;
        #pragma unroll
        for (int kk = 0; kk < 16; kk += 2) {
            float2 w0 = *(const float2*)&W[kk*132 + mloc];
            float2 w1 = *(const float2*)&W[(kk+1)*132 + mloc];
            float2 x0 = *(const float2*)(i0 + kk);
            float2 x1 = *(const float2*)(i0 + pitch + kk);
            float2 x2 = *(const float2*)(i0 + 2*pitch + kk);
            float2 x3 = *(const float2*)(i0 + 3*pitch + kk);
            acc[0] = fmaf(x0.x, w0.x, acc[0]); acc[0] = fmaf(x0.y, w1.x, acc[0]);
            acc[1] = fmaf(x0.x, w0.y, acc[1]); acc[1] = fmaf(x0.y, w1.y, acc[1]);
            acc[2] = fmaf(x1.x, w0.x, acc[2]); acc[2] = fmaf(x1.y, w1.x, acc[2]);
            acc[3] = fmaf(x1.x, w0.y, acc[3]); acc[3] = fmaf(x1.y, w1.y, acc[3]);
            acc[4] = fmaf(x2.x, w0.x, acc[4]); acc[4] = fmaf(x2.y, w1.x, acc[4]);
            acc[5] = fmaf(x2.x, w0.y, acc[5]); acc[5] = fmaf(x2.y, w1.y, acc[5]);
            acc[6] = fmaf(x3.x, w0.x, acc[6]); acc[6] = fmaf(x3.y, w1.x, acc[6]);
            acc[7] = fmaf(x3.x, w0.y, acc[7]); acc[7] = fmaf(x3.y, w1.y, acc[7]);
        }
        buf ^= 1;
    }
    __syncthreads();               // all tile reads done (enables in-place store + Wt reuse)
    if (fin && mloc < Mreal) {
        float2 bb = *(const float2*)&bias[mloc];
        int r0 = rg*4;
        float2 o;
        o.x = acc[0]+bb.x; o.y = acc[1]+bb.y;
        if (act) { o.x = gelu_f(o.x); o.y = gelu_f(o.y); }
        *(float2*)&smOut[(size_t)(r0+0)*opitch + mloc] = o;
        o.x = acc[2]+bb.x; o.y = acc[3]+bb.y;
        if (act) { o.x = gelu_f(o.x); o.y = gelu_f(o.y); }
        *(float2*)&smOut[(size_t)(r0+1)*opitch + mloc] = o;
        o.x = acc[4]+bb.x; o.y = acc[5]+bb.y;
        if (act) { o.x = gelu_f(o.x); o.y = gelu_f(o.y); }
        *(float2*)&smOut[(size_t)(r0+2)*opitch + mloc] = o;
        o.x = acc[6]+bb.x; o.y = acc[7]+bb.y;
        if (act) { o.x = gelu_f(o.x); o.y = gelu_f(o.y); }
        *(float2*)&smOut[(size_t)(r0+3)*opitch + mloc] = o;
    }
}

// Large GEMM: OUT[16 x 256] = IN[16 x K] @ Wk (k-major, row stride wrow) + bias, opt GELU.
// 8x2 microtile, single m-block of 256, cp.async double-buffer, one barrier/tile.
__device__ __forceinline__ void gemm_l(
    const float* smIn, int pitch, int K,
    const float* __restrict__ Wk, int wrow,
    const float* __restrict__ bias,
    float* smOut, int opitch, int act, float* Wt)
{
    const int tid = threadIdx.x;
    const int mloc = (tid & 127) << 1;
    const int rg = tid >> 7;
    const int srow = tid >> 6;            // staging rows srow + 4s
    const int scol = (tid & 63) << 2;
    const float* inb = smIn + rg*8*pitch;
    const int T = K >> 4;
    {
        #pragma unroll
        for (int s4 = 0; s4 < 4; s4++) {
            uint32_t d = smem_u32(Wt + (srow + 4*s4)*260 + scol);
            CP_ASYNC16(d, Wk + (size_t)(srow + 4*s4)*wrow + scol);
        }
        CP_COMMIT();
    }
    float acc[16];
    #pragma unroll
    for (int i = 0; i < 16; i++) acc[i] = 0.f;
    int buf = 0;
    for (int t = 0; t < T; t++) {
        CP_WAIT0();
        __syncthreads();
        if (t + 1 < T) {
            const float* g = Wk + (size_t)((t+1)*16)*wrow;
            float* Wd = Wt + (buf^1)*4160;
            #pragma unroll
            for (int s4 = 0; s4 < 4; s4++) {
                uint32_t d = smem_u32(Wd + (srow + 4*s4)*260 + scol);
                CP_ASYNC16(d, g + (size_t)(srow + 4*s4)*wrow + scol);
            }
            CP_COMMIT();
        }
        const float* W = Wt + buf*4160;
        const float* ix = inb + t*16;
        #pragma unroll
        for (int kk = 0; kk < 16; kk += 2) {
            float2 w0 = *(const float2*)&W[kk*260 + mloc];
            float2 w1 = *(const float2*)&W[(kk+1)*260 + mloc];
            #pragma unroll
            for (int r = 0; r < 8; r++) {
                float2 x = *(const float2*)(ix + r*pitch + kk);
                acc[2*r]   = fmaf(x.x, w0.x, acc[2*r]);
                acc[2*r]   = fmaf(x.y, w1.x, acc[2*r]);
                acc[2*r+1] = fmaf(x.x, w0.y, acc[2*r+1]);
                acc[2*r+1] = fmaf(x.y, w1.y, acc[2*r+1]);
            }
        }
        buf ^= 1;
    }
    __syncthreads();
    float2 bb = *(const float2*)&bias[mloc];
    #pragma unroll
    for (int r = 0; r < 8; r++) {
        float2 o;
        o.x = acc[2*r] + bb.x; o.y = acc[2*r+1] + bb.y;
        if (act) { o.x = gelu_f(o.x); o.y = gelu_f(o.y); }
        *(float2*)&smOut[(size_t)(rg*8 + r)*opitch + mloc] = o;
    }
}

__global__ void __launch_bounds__(NT, 3) fused_kernel(
    const float* __restrict__ x_enc, const float* __restrict__ eps,
    const float* __restrict__ p_aw, const float* __restrict__ p_ab,
    const float* __restrict__ b_sc,
    const float* __restrict__ b_r1, const float* __restrict__ b_r2,
    const float* __restrict__ b_r3,
    const float* __restrict__ flow_w, const float* __restrict__ flow_b,
    float* __restrict__ out)
{
    extern __shared__ float smn[];
    float* sA    = smn + P_A;
    float* sINP  = smn + P_A;       // [z | h], pitch 192, aliases xn
    float* sPB   = smn + P_PB;
    float* sMean = smn + P_MEAN;
    float* sStd  = smn + P_STD;
    float* sScale= smn + P_SCALE;
    float* sB    = smn + P_B;
    float* sWT   = smn + P_WT;

    int tid = threadIdx.x;
    int n0 = blockIdx.x * ROWS;
    float aw = p_aw[0], ab = p_ab[0];
    int warp = tid >> 5, lane = tid & 31;
    float acc[8];

    // ---- 1. load x (x_enc[b][l][c] -> xn_raw[r][l], n = b*7+c) ----
    for (int t = tid; t < ROWS*L; t += NT) {
        int r = t & 15, l = t >> 4;
        int n = n0 + r;
        int b = n / 7, c = n - b*7;
        sA[r*L + l] = x_enc[(b*L + l)*7 + c];
    }
    __syncthreads();

    // ---- 2. per-row mean/std ----
    #pragma unroll
    for (int rr = 0; rr < 2; rr++) {
        int r = warp*2 + rr;
        const float* row = sA + r*L;
        float s = 0.f, sq = 0.f;
        for (int l2 = lane; l2 < L; l2 += 32) { float v = row[l2]; s += v; sq += v*v; }
        #pragma unroll
        for (int o = 16; o > 0; o >>= 1) {
            s  += __shfl_xor_sync(0xffffffffu, s, o);
            sq += __shfl_xor_sync(0xffffffffu, sq, o);
        }
        if (lane == 0) {
            float mean = s * (1.f/336.f);
            float var = sq * (1.f/336.f) - mean*mean;
            float sd = sqrtf(var + 1e-5f);
            sMean[r] = mean; sStd[r] = sd; sScale[r] = aw / sd;
        }
    }
    __syncthreads();

    // ---- 3. normalize in place ----
    for (int t = tid; t < ROWS*L; t += NT) {
        int r = t / L;
        sA[t] = (sA[t] - sMean[r]) * sScale[r] + ab;
    }
    __syncthreads();

    // ---- 4. pbar[r][j] = mean over 41 patches ----
    {
        int r = tid >> 4, j = tid & 15;
        float s = 0.f;
        #pragma unroll
        for (int pp = 0; pp < 41; pp++) s += sA[r*L + pp*8 + j];
        sPB[r*16 + j] = s * (1.f/41.f);
    }
    // (gemm internal barriers order pbar/xn before reads)

    // ---- 5. shortcut = xn @ Wsc^T + b_sc  -> gmem scratch ----
    gemm_s(sA, L, L, g_Wsct, b_sc, 96, g_short + (size_t)n0*96, 96, 0, sWT, acc, 1, 1);
    // ---- 6. h = pbar @ Wc^T + bc  -> inp[:,64:192] ----
    gemm_s(sPB, 16, 16, g_Wct, g_bc, 128, sINP + 64, 192, 0, sWT, acc, 1, 1);
    // ---- 7. [mu|lv] = h @ Wml^T + bml ----
    gemm_s(sINP + 64, 192, 128, g_Wmlt, g_bml, 128, sB, 128, 0, sWT, acc, 1, 1);
    __syncthreads();

    // ---- 8+9. reparam (FP64) + planar flows (FP64 scalar chain) ----
    #pragma unroll
    for (int rr = 0; rr < 2; rr++) {
        int r = warp + rr*8;
        int n = n0 + r;
        float mu0 = sB[r*128 + lane];
        float mu1 = sB[r*128 + 32 + lane];
        float lv0 = sB[r*128 + 64 + lane];
        float lv1 = sB[r*128 + 96 + lane];
        out[OFF_MU + n*64 + lane]      = mu0;
        out[OFF_MU + n*64 + 32 + lane] = mu1;
        out[OFF_LV + n*64 + lane]      = lv0;
        out[OFF_LV + n*64 + 32 + lane] = lv1;
        double z0 = (double)mu0 + (double)eps[n*64 + lane]      * exp(0.5 * (double)lv0);
        double z1 = (double)mu1 + (double)eps[n*64 + 32 + lane] * exp(0.5 * (double)lv1);
        double ld = 0.0;
        #pragma unroll
        for (int i = 0; i < 8; i++) {
            double w0 = (double)flow_w[i*64 + lane];
            double w1 = (double)flow_w[i*64 + 32 + lane];
            double dot = z0*w0 + z1*w1;
            #pragma unroll
            for (int o = 16; o > 0; o >>= 1) dot += __shfl_xor_sync(0xffffffffu, dot, o);
            double th = tanh(dot + (double)flow_b[i]);
            z0 += th * g_uhat[i*64 + lane];
            z1 += th * g_uhat[i*64 + 32 + lane];
            ld += log(fabs(1.0 + (1.0 - th*th) * g_cflow[i]) + 1e-6);
        }
        sINP[r*192 + lane]      = (float)z0;
        sINP[r*192 + 32 + lane] = (float)z1;
        if (lane == 0) out[OFF_LD + n] = (float)ld;
    }
    // (flows write sINP/read sB; r1's first internal barrier orders)

    // ---- 10. r1 = gelu(inp @ Wr1^T + br1) -> sB ----
    gemm_l(sINP, 192, 192, g_Wr1t, 256, b_r1, sB, 256, 1, sWT);

    // ---- 11+12. r2 (2 chunks of 256) fused with r3 accumulation ----
    {
        float acc3[8];
        #pragma unroll
        for (int c = 0; c < 2; c++) {
            // r2 chunk: output cols 256c..256c+256 -> gelu -> sA[16][256]
            gemm_l(sB, 256, 256, g_Wr2t + 256*c, 512, b_r2 + 256*c, sA, 256, 1, sWT);
            // r3 partial: acc3 += r2chunk @ Wr3t[256c:256c+256][:]
            gemm_s(sA, 256, 256, g_Wr3t + (size_t)(256*c)*128, b_r3, 96,
                   sA, 96, 0, sWT, acc3, c == 0, c == 1);
        }
    }
    __syncthreads();

    // ---- 13. denorm + scatter out[b][p][c] (recon in sA[16][96]) ----
    float inv_aw = 1.f / (aw + 1e-10f);
    for (int t = tid; t < ROWS*96; t += NT) {
        int r = t & 15, pcol = t >> 4;
        int n = n0 + r;
        float v = sA[r*96 + pcol] + g_short[(size_t)n*96 + pcol];
        float den = fmaf((v - ab) * inv_aw, sStd[r], sMean[r]);
        int b = n/7, c = n - b*7;
        out[(b*96 + pcol)*7 + c] = den;
    }
}

extern "C" void kernel_launch(void* const* d_in, const int* in_sizes, int n_in,
                              void* d_out, int out_size) {
    const float* x_enc  = (const float*)d_in[0];
    const float* eps    = (const float*)d_in[1];
    const float* aw     = (const float*)d_in[2];
    const float* ab     = (const float*)d_in[3];
    const float* W_sc   = (const float*)d_in[4];
    const float* b_sc   = (const float*)d_in[5];
    const float* W_ts   = (const float*)d_in[6];
    const float* b_ts   = (const float*)d_in[7];
    const float* W_fu   = (const float*)d_in[8];
    const float* b_fu   = (const float*)d_in[9];
    const float* W_mu   = (const float*)d_in[10];
    const float* b_mu   = (const float*)d_in[11];
    const float* W_lv   = (const float*)d_in[12];
    const float* b_lv   = (const float*)d_in[13];
    const float* flow_u = (const float*)d_in[14];
    const float* flow_w = (const float*)d_in[15];
    const float* flow_b = (const float*)d_in[16];
    const float* W_r1   = (const float*)d_in[17];
    const float* b_r1   = (const float*)d_in[18];
    const float* W_r2   = (const float*)d_in[19];
    const float* b_r2   = (const float*)d_in[20];
    const float* W_r3   = (const float*)d_in[21];
    const float* b_r3   = (const float*)d_in[22];
    float* out = (float*)d_out;

    cudaFuncSetAttribute(fused_kernel, cudaFuncAttributeMaxDynamicSharedMemorySize, SMEM_BYTES);

    prep_kernel<<<128, 256>>>(W_sc, W_mu, b_mu, W_lv, b_lv, W_r3,
                              W_fu, b_fu, W_ts, b_ts, flow_u, flow_w, W_r1, W_r2);
    fused_kernel<<<448, NT, SMEM_BYTES>>>(x_enc, eps, aw, ab, b_sc,
                                          b_r1, b_r2, b_r3,
                                          flow_w, flow_b, out);
}